// round 13
// baseline (speedup 1.0000x reference)
#include <cuda_runtime.h>

#define NN 100000
#define EE 600000
#define DD 128
#define SCAN_BLOCKS 98   // ceil(100000/1024)
#define GTILES ((NN + 15) / 16)

typedef unsigned long long u64;

// ---------------- scratch (static __device__, no allocation) ----------------
__device__ float g_h[(size_t)NN * DD];
__device__ float g_acc[(size_t)NN * DD];
__device__ float g_dinv[NN];
__device__ int   g_deg[NN];
__device__ int   g_rowstart[NN];
__device__ int   g_pos[NN];
__device__ int   g_bsum[128];
__device__ int   g_flag[128];
__device__ int   g_ticket;
__device__ int   g_done;
__device__ int2  g_emeta[EE];
__device__ float g_colsum[DD];
__device__ float g_colsumsq[DD];
__device__ float g_scale[DD];
__device__ float g_shift[DD];
__device__ int   g_ei32;

// ---------------- edge index decode (32-bit low-word path) ----------------
__device__ __forceinline__ int load_src(const void* ei, int e) {
    return g_ei32 ? ((const int*)ei)[e] : ((const int*)ei)[2 * e];
}
__device__ __forceinline__ int load_dst(const void* ei, int e) {
    return g_ei32 ? ((const int*)ei)[EE + e] : ((const int*)ei)[2 * (EE + e)];
}

// ---------------- prep: zero scratch + dtype sniff (block 0) --------------
__global__ void k_prep(const void* ei) {
    int i = blockIdx.x * blockDim.x + threadIdx.x;
    if (i < NN) g_deg[i] = 0;
    if (i < DD) { g_colsum[i] = 0.f; g_colsumsq[i] = 0.f; }
    if (i < 128) g_flag[i] = 0;
    if (i == 0) { g_ticket = 0; g_done = 0; }
    if (blockIdx.x == 0) {
        const long long* p = (const long long*)ei;
        int t = threadIdx.x;
        int bad = 0;
#pragma unroll
        for (int j = 0; j < 4; j++) {
            long long v = p[t * 4 + j];
            if (v < 0 || v >= NN) bad = 1;
        }
        unsigned m = __ballot_sync(0xFFFFFFFFu, bad);
        __shared__ int s_bad;
        if (t == 0) s_bad = 0;
        __syncthreads();
        if (m && (t & 31) == 0) atomicOr(&s_bad, 1);
        __syncthreads();
        if (t == 0) g_ei32 = s_bad;
    }
}

__global__ void k_degree(const void* __restrict__ ei) {
    int i = blockIdx.x * blockDim.x + threadIdx.x;
    if (i < EE) {
        int d = load_dst(ei, i);
        if ((unsigned)d < NN) atomicAdd(&g_deg[d], 1);
    }
}

// ---------------- fused scan: deg -> rowstart/pos/dinv --------------------
__global__ void k_scanF() {
    __shared__ int s_warp[32];
    __shared__ int s_bsum[SCAN_BLOCKS];
    __shared__ int s_off;
    int t = threadIdx.x;
    int lane = t & 31;
    int wid = t >> 5;
    int blk = blockIdx.x;
    int i = blk * 1024 + t;
    int v = (i < NN) ? g_deg[i] : 0;
    int sc = v;
#pragma unroll
    for (int off = 1; off < 32; off <<= 1) {
        int n = __shfl_up_sync(0xFFFFFFFFu, sc, off);
        if (lane >= off) sc += n;
    }
    if (lane == 31) s_warp[wid] = sc;
    __syncthreads();
    if (wid == 0) {
        int ws = s_warp[lane];
#pragma unroll
        for (int off = 1; off < 32; off <<= 1) {
            int n = __shfl_up_sync(0xFFFFFFFFu, ws, off);
            if (lane >= off) ws += n;
        }
        s_warp[lane] = ws;
    }
    __syncthreads();
    int base = (wid > 0) ? s_warp[wid - 1] : 0;
    if (t == 1023) {
        g_bsum[blk] = base + sc;
        __threadfence();
        atomicExch(&g_flag[blk], 1);
    }
    if (t < SCAN_BLOCKS) {
        while (atomicAdd(&g_flag[t], 0) == 0) { }
        s_bsum[t] = g_bsum[t];
    }
    __syncthreads();
    if (t == 0) {
        int r = 0;
        for (int j = 0; j < blk; j++) r += s_bsum[j];
        s_off = r;
    }
    __syncthreads();
    if (i < NN) {
        int rs = s_off + base + sc - v;
        g_rowstart[i] = rs;
        g_pos[i] = rs;
        g_dinv[i] = rsqrtf((float)g_deg[i] + 1.0f);
    }
}

__global__ void k_fill(const void* __restrict__ ei) {
    int e = blockIdx.x * blockDim.x + threadIdx.x;
    if (e >= EE) return;
    int src = load_src(ei, e);
    int dst = load_dst(ei, e);
    if ((unsigned)src >= NN || (unsigned)dst >= NN) return;
    float nrm = g_dinv[src] * g_dinv[dst];
    int slot = atomicAdd(&g_pos[dst], 1);
    g_emeta[slot] = make_int2(src, __float_as_int(nrm));
}

// ---------------- GEMM: tf32 mma.sync, fragment-ordered smem --------------
// Smem holds tiles pre-swizzled into exact fragment order: each thread's
// A-frag = one LDS.128, B-frag = one LDS.64. Double-buffered chunks of K=16.
// A word order (a0,a1,a2,a3) = (r<8,k<4),(r>=8,k<4),(r<8,k>=4),(r>=8,k>=4).
__device__ __forceinline__ unsigned tf32cvt(float f) {
    unsigned r; asm("cvt.rna.tf32.f32 %0, %1;" : "=r"(r) : "f"(f)); return r;
}

__global__ void __launch_bounds__(256, 2)
k_gemm(const float* __restrict__ X, const float* __restrict__ W) {
    // Xs: [8 m-tiles][2 ksteps][32 lanes][4 words]  = 2048 words / buffer
    // Ws: [16 n-tiles][2 ksteps][32 lanes][2 words] = 2048 words / buffer
    __shared__ unsigned Xs[2][2048];
    __shared__ unsigned Ws[2][2048];
    const int tid  = threadIdx.x;
    const int lane = tid & 31;
    const int warp = tid >> 5;
    const int g    = lane >> 2;
    const int t4   = lane & 3;
    const int wmT  = (warp & 1) * 4;     // first m-tile of warp (x16 rows)
    const int wnT  = (warp >> 1) * 4;    // first n-tile of warp (x8 cols)
    const int wm   = wmT * 16;
    const int wn   = wnT * 8;
    const int rowBase = blockIdx.x * 128;

    float acc[4][4][4];
#pragma unroll
    for (int i = 0; i < 4; i++)
#pragma unroll
        for (int j = 0; j < 4; j++)
#pragma unroll
            for (int c = 0; c < 4; c++) acc[i][j][c] = 0.f;

    auto stage = [&](int kc, int bb) {
        // W chunk [16 k x 128 n]
#pragma unroll
        for (int i = 0; i < 8; i++) {
            int idx = tid + 256 * i;
            int kl = idx >> 7;              // 0..15
            int n  = idx & 127;
            int ntile = n >> 3, gc = n & 7;
            int kstep = kl >> 3, k8 = kl & 7;
            int tt = k8 & 3, hk = k8 >> 2;  // word = hk
            int dst = ((ntile * 2 + kstep) * 32 + (gc * 4 + tt)) * 2 + hk;
            Ws[bb][dst] = tf32cvt(W[(size_t)(kc * 16 + kl) * DD + n]);
        }
        // X chunk [128 r x 16 k]
#pragma unroll
        for (int i = 0; i < 8; i++) {
            int idx = tid + 256 * i;
            int r  = idx >> 4;              // 0..127
            int kl = idx & 15;
            int row = rowBase + r;
            float xv = (row < NN) ? X[(size_t)row * DD + kc * 16 + kl] : 0.f;
            int tile = r >> 4, rr = r & 15;
            int gg = rr & 7, hr = rr >> 3;
            int kstep = kl >> 3, k8 = kl & 7;
            int tt = k8 & 3, hk = k8 >> 2;
            int dst = ((tile * 2 + kstep) * 32 + (gg * 4 + tt)) * 4 + (hr + 2 * hk);
            Xs[bb][dst] = tf32cvt(xv);
        }
    };

    stage(0, 0);
    __syncthreads();

    for (int kc = 0; kc < 8; kc++) {
        int bb = kc & 1;
        if (kc + 1 < 8) stage(kc + 1, bb ^ 1);
#pragma unroll
        for (int ks = 0; ks < 2; ks++) {
            uint2 bf[4];
#pragma unroll
            for (int j = 0; j < 4; j++)
                bf[j] = *(const uint2*)&Ws[bb][((wnT + j) * 2 + ks) * 64 + lane * 2];
#pragma unroll
            for (int i = 0; i < 4; i++) {
                uint4 av = *(const uint4*)&Xs[bb][((wmT + i) * 2 + ks) * 128 + lane * 4];
#pragma unroll
                for (int j = 0; j < 4; j++) {
                    asm volatile(
                        "mma.sync.aligned.m16n8k8.row.col.f32.tf32.tf32.f32 "
                        "{%0,%1,%2,%3}, {%4,%5,%6,%7}, {%8,%9}, {%0,%1,%2,%3};"
                        : "+f"(acc[i][j][0]), "+f"(acc[i][j][1]),
                          "+f"(acc[i][j][2]), "+f"(acc[i][j][3])
                        : "r"(av.x), "r"(av.y), "r"(av.z), "r"(av.w),
                          "r"(bf[j].x), "r"(bf[j].y));
                }
            }
        }
        __syncthreads();
    }

#pragma unroll
    for (int i = 0; i < 4; i++) {
        int rbase = rowBase + wm + i * 16 + g;
#pragma unroll
        for (int half = 0; half < 2; half++) {
            int r = rbase + half * 8;
            if (r < NN) {
                float2* p = (float2*)(g_h + (size_t)r * DD + wn);
#pragma unroll
                for (int j = 0; j < 4; j++)
                    p[j * 4 + t4] = make_float2(acc[i][j][half * 2],
                                                acc[i][j][half * 2 + 1]);
            }
        }
    }
}

// ---------------- persistent gather + BN + final (grid = 148, all resident)
__global__ void __launch_bounds__(512, 1)
k_gatherF(const float* __restrict__ b,
          const float* __restrict__ gamma,
          const float* __restrict__ beta,
          const float* __restrict__ X,
          float* __restrict__ out) {
    __shared__ float s_sum[DD];
    __shared__ float s_sumsq[DD];
    __shared__ int s_last;
    int t = threadIdx.x;
    if (t < DD) { s_sum[t] = 0.f; s_sumsq[t] = 0.f; }
    __syncthreads();

    int lane = t & 31;
    int warp = t >> 5;
    float4 bb = __ldg(&((const float4*)b)[lane]);

    // ---- phase 1: gather + per-block BN partials ----
    for (int tile = blockIdx.x; tile < GTILES; tile += gridDim.x) {
        int node = tile * 16 + warp;
        if (node >= NN) continue;
        float dv = g_dinv[node];
        float4 hv = __ldg(&((const float4*)(g_h + (size_t)node * DD))[lane]);
        float nrm0 = dv * dv;
        float4 a = make_float4(hv.x * nrm0 + bb.x, hv.y * nrm0 + bb.y,
                               hv.z * nrm0 + bb.z, hv.w * nrm0 + bb.w);
        int e   = g_rowstart[node];
        int end = e + g_deg[node];
        if (e + 3 < end) {
            int2 m0 = __ldg(&g_emeta[e]),     m1 = __ldg(&g_emeta[e + 1]);
            int2 m2 = __ldg(&g_emeta[e + 2]), m3 = __ldg(&g_emeta[e + 3]);
            for (;;) {
                int en = e + 4;
                bool more = (en + 3 < end);
                int2 p0, p1, p2, p3;
                if (more) {
                    p0 = __ldg(&g_emeta[en]);     p1 = __ldg(&g_emeta[en + 1]);
                    p2 = __ldg(&g_emeta[en + 2]); p3 = __ldg(&g_emeta[en + 3]);
                }
                float4 v0 = __ldg(&((const float4*)(g_h + (size_t)m0.x * DD))[lane]);
                float4 v1 = __ldg(&((const float4*)(g_h + (size_t)m1.x * DD))[lane]);
                float4 v2 = __ldg(&((const float4*)(g_h + (size_t)m2.x * DD))[lane]);
                float4 v3 = __ldg(&((const float4*)(g_h + (size_t)m3.x * DD))[lane]);
                float n0 = __int_as_float(m0.y), n1 = __int_as_float(m1.y);
                float n2 = __int_as_float(m2.y), n3 = __int_as_float(m3.y);
                a.x += v0.x * n0; a.y += v0.y * n0; a.z += v0.z * n0; a.w += v0.w * n0;
                a.x += v1.x * n1; a.y += v1.y * n1; a.z += v1.z * n1; a.w += v1.w * n1;
                a.x += v2.x * n2; a.y += v2.y * n2; a.z += v2.z * n2; a.w += v2.w * n2;
                a.x += v3.x * n3; a.y += v3.y * n3; a.z += v3.z * n3; a.w += v3.w * n3;
                e = en;
                if (!more) break;
                m0 = p0; m1 = p1; m2 = p2; m3 = p3;
            }
        }
        for (; e < end; e++) {
            int2 m = __ldg(&g_emeta[e]);
            float nrm = __int_as_float(m.y);
            float4 v = __ldg(&((const float4*)(g_h + (size_t)m.x * DD))[lane]);
            a.x += v.x * nrm; a.y += v.y * nrm;
            a.z += v.z * nrm; a.w += v.w * nrm;
        }
        ((float4*)(g_acc + (size_t)node * DD))[lane] = a;
        int c = lane * 4;
        atomicAdd(&s_sum[c + 0], a.x); atomicAdd(&s_sumsq[c + 0], a.x * a.x);
        atomicAdd(&s_sum[c + 1], a.y); atomicAdd(&s_sumsq[c + 1], a.y * a.y);
        atomicAdd(&s_sum[c + 2], a.z); atomicAdd(&s_sumsq[c + 2], a.z * a.z);
        atomicAdd(&s_sum[c + 3], a.w); atomicAdd(&s_sumsq[c + 3], a.w * a.w);
    }
    __syncthreads();
    if (t < DD)            atomicAdd(&g_colsum[t], s_sum[t]);
    else if (t < 2 * DD)   atomicAdd(&g_colsumsq[t - DD], s_sumsq[t - DD]);

    // ---- grid-wide sync (all 148 blocks resident: 1 CTA/SM) ----
    __threadfence();
    __syncthreads();
    if (t == 0) s_last = (atomicAdd(&g_ticket, 1) == (int)gridDim.x - 1);
    __syncthreads();
    if (s_last) {
        if (t < DD) {
            float mean = g_colsum[t] * (1.0f / (float)NN);
            float var  = g_colsumsq[t] * (1.0f / (float)NN) - mean * mean;
            float rstd = rsqrtf(var + 1e-5f);
            float sc   = rstd * gamma[t];
            g_scale[t] = sc;
            g_shift[t] = beta[t] - mean * sc;
        }
        __threadfence();
        __syncthreads();
        if (t == 0) atomicExch(&g_done, 1);
    }
    if (t == 0) { while (atomicAdd(&g_done, 0) == 0) { } }
    __syncthreads();

    // ---- phase 2: out = relu(acc*scale + shift) + x ----
    float4 sc = ((const float4*)g_scale)[lane];
    float4 sh = ((const float4*)g_shift)[lane];
    for (int tile = blockIdx.x; tile < GTILES; tile += gridDim.x) {
        int node = tile * 16 + warp;
        if (node >= NN) continue;
        size_t off = (size_t)node * DD;
        float4 a  = ((const float4*)(g_acc + off))[lane];
        float4 xv = __ldg(&((const float4*)(X + off))[lane]);
        float4 o;
        o.x = fmaxf(a.x * sc.x + sh.x, 0.f) + xv.x;
        o.y = fmaxf(a.y * sc.y + sh.y, 0.f) + xv.y;
        o.z = fmaxf(a.z * sc.z + sh.z, 0.f) + xv.z;
        o.w = fmaxf(a.w * sc.w + sh.w, 0.f) + xv.w;
        ((float4*)(out + off))[lane] = o;
    }
}

// ---------------- launch ----------------
extern "C" void kernel_launch(void* const* d_in, const int* in_sizes, int n_in,
                              void* d_out, int out_size) {
    const float* x = nullptr; const void* ei = nullptr; const float* W = nullptr;
    const float* b = nullptr; const float* gamma = nullptr; const float* beta = nullptr;
    for (int i = 0; i < n_in; i++) {
        int sz = in_sizes[i];
        if (sz == NN * DD)      x  = (const float*)d_in[i];
        else if (sz == 2 * EE)  ei = d_in[i];
        else if (sz == DD * DD) W  = (const float*)d_in[i];
        else if (sz == DD) {
            if (!b) b = (const float*)d_in[i];
            else if (!gamma) gamma = (const float*)d_in[i];
            else beta = (const float*)d_in[i];
        }
    }
    float* out = (float*)d_out;

    static cudaStream_t s_side = nullptr;
    static cudaEvent_t ev_fork = nullptr, ev_join = nullptr;
    if (!s_side) {
        cudaStreamCreateWithFlags(&s_side, cudaStreamNonBlocking);
        cudaEventCreateWithFlags(&ev_fork, cudaEventDisableTiming);
        cudaEventCreateWithFlags(&ev_join, cudaEventDisableTiming);
    }

    // Fork: tensor-core GEMM overlaps the edge-prep chain.
    cudaEventRecord(ev_fork, 0);
    cudaStreamWaitEvent(s_side, ev_fork, 0);
    k_gemm<<<(NN + 127) / 128, 256, 0, s_side>>>(x, W);
    cudaEventRecord(ev_join, s_side);

    // Edge-prep chain.
    k_prep<<<(NN + 255) / 256, 256>>>(ei);
    k_degree<<<(EE + 255) / 256, 256>>>(ei);
    k_scanF<<<SCAN_BLOCKS, 1024>>>();
    k_fill<<<(EE + 255) / 256, 256>>>(ei);

    // Join, then persistent gather+BN+final.
    cudaStreamWaitEvent(0, ev_join, 0);
    k_gatherF<<<148, 512>>>(b, gamma, beta, x, out);
}

// round 16
// speedup vs baseline: 1.1088x; 1.1088x over previous
#include <cuda_runtime.h>

#define NN 100000
#define EE 600000
#define DD 128
#define SCAN_BLOCKS 98   // ceil(100000/1024)
#define GT32 3125        // NN / 32 exactly

typedef unsigned long long u64;

// ---------------- scratch (static __device__, no allocation) ----------------
__device__ float g_h[(size_t)NN * DD];
__device__ float g_acc[(size_t)NN * DD];
__device__ float g_dinv[NN];
__device__ int   g_deg[NN];
__device__ int   g_rowstart[NN];
__device__ int   g_pos[NN];
__device__ int   g_bsum[128];
__device__ int   g_flag[128];
__device__ int   g_ticket;
__device__ int   g_done;
__device__ int2  g_emeta[EE];
__device__ float g_colsum[DD];
__device__ float g_colsumsq[DD];
__device__ float g_scale[DD];
__device__ float g_shift[DD];
__device__ int   g_ei32;

// ---------------- edge index decode (32-bit low-word path) ----------------
__device__ __forceinline__ int load_src(const void* ei, int e) {
    return g_ei32 ? ((const int*)ei)[e] : ((const int*)ei)[2 * e];
}
__device__ __forceinline__ int load_dst(const void* ei, int e) {
    return g_ei32 ? ((const int*)ei)[EE + e] : ((const int*)ei)[2 * (EE + e)];
}

// ---------------- prep: zero scratch + dtype sniff (block 0) --------------
__global__ void k_prep(const void* ei) {
    int i = blockIdx.x * blockDim.x + threadIdx.x;
    if (i < NN) g_deg[i] = 0;
    if (i < DD) { g_colsum[i] = 0.f; g_colsumsq[i] = 0.f; }
    if (i < 128) g_flag[i] = 0;
    if (i == 0) { g_ticket = 0; g_done = 0; }
    if (blockIdx.x == 0) {
        const long long* p = (const long long*)ei;
        int t = threadIdx.x;
        int bad = 0;
#pragma unroll
        for (int j = 0; j < 4; j++) {
            long long v = p[t * 4 + j];
            if (v < 0 || v >= NN) bad = 1;
        }
        unsigned m = __ballot_sync(0xFFFFFFFFu, bad);
        __shared__ int s_bad;
        if (t == 0) s_bad = 0;
        __syncthreads();
        if (m && (t & 31) == 0) atomicOr(&s_bad, 1);
        __syncthreads();
        if (t == 0) g_ei32 = s_bad;
    }
}

__global__ void k_degree(const void* __restrict__ ei) {
    int i = blockIdx.x * blockDim.x + threadIdx.x;
    if (i < EE) {
        int d = load_dst(ei, i);
        if ((unsigned)d < NN) atomicAdd(&g_deg[d], 1);
    }
}

// ---------------- fused scan: deg -> rowstart/pos/dinv --------------------
__global__ void k_scanF() {
    __shared__ int s_warp[32];
    __shared__ int s_bsum[SCAN_BLOCKS];
    __shared__ int s_off;
    int t = threadIdx.x;
    int lane = t & 31;
    int wid = t >> 5;
    int blk = blockIdx.x;
    int i = blk * 1024 + t;
    int v = (i < NN) ? g_deg[i] : 0;
    int sc = v;
#pragma unroll
    for (int off = 1; off < 32; off <<= 1) {
        int n = __shfl_up_sync(0xFFFFFFFFu, sc, off);
        if (lane >= off) sc += n;
    }
    if (lane == 31) s_warp[wid] = sc;
    __syncthreads();
    if (wid == 0) {
        int ws = s_warp[lane];
#pragma unroll
        for (int off = 1; off < 32; off <<= 1) {
            int n = __shfl_up_sync(0xFFFFFFFFu, ws, off);
            if (lane >= off) ws += n;
        }
        s_warp[lane] = ws;
    }
    __syncthreads();
    int base = (wid > 0) ? s_warp[wid - 1] : 0;
    if (t == 1023) {
        g_bsum[blk] = base + sc;
        __threadfence();
        atomicExch(&g_flag[blk], 1);
    }
    if (t < SCAN_BLOCKS) {
        while (atomicAdd(&g_flag[t], 0) == 0) { }
        s_bsum[t] = g_bsum[t];
    }
    __syncthreads();
    if (t == 0) {
        int r = 0;
        for (int j = 0; j < blk; j++) r += s_bsum[j];
        s_off = r;
    }
    __syncthreads();
    if (i < NN) {
        int rs = s_off + base + sc - v;
        g_rowstart[i] = rs;
        g_pos[i] = rs;
        g_dinv[i] = rsqrtf((float)g_deg[i] + 1.0f);
    }
}

__global__ void k_fill(const void* __restrict__ ei) {
    int e = blockIdx.x * blockDim.x + threadIdx.x;
    if (e >= EE) return;
    int src = load_src(ei, e);
    int dst = load_dst(ei, e);
    if ((unsigned)src >= NN || (unsigned)dst >= NN) return;
    float nrm = g_dinv[src] * g_dinv[dst];
    int slot = atomicAdd(&g_pos[dst], 1);
    g_emeta[slot] = make_int2(src, __float_as_int(nrm));
}

// ---------------- GEMM: tf32 mma.sync, fragment-ordered smem --------------
__device__ __forceinline__ unsigned tf32cvt(float f) {
    unsigned r; asm("cvt.rna.tf32.f32 %0, %1;" : "=r"(r) : "f"(f)); return r;
}

__global__ void __launch_bounds__(256, 2)
k_gemm(const float* __restrict__ X, const float* __restrict__ W) {
    __shared__ unsigned Xs[2][2048];
    __shared__ unsigned Ws[2][2048];
    const int tid  = threadIdx.x;
    const int lane = tid & 31;
    const int warp = tid >> 5;
    const int g    = lane >> 2;
    const int t4   = lane & 3;
    const int wmT  = (warp & 1) * 4;
    const int wnT  = (warp >> 1) * 4;
    const int wm   = wmT * 16;
    const int wn   = wnT * 8;
    const int rowBase = blockIdx.x * 128;

    float acc[4][4][4];
#pragma unroll
    for (int i = 0; i < 4; i++)
#pragma unroll
        for (int j = 0; j < 4; j++)
#pragma unroll
            for (int c = 0; c < 4; c++) acc[i][j][c] = 0.f;

    auto stage = [&](int kc, int bb) {
#pragma unroll
        for (int i = 0; i < 8; i++) {
            int idx = tid + 256 * i;
            int kl = idx >> 7;
            int n  = idx & 127;
            int ntile = n >> 3, gc = n & 7;
            int kstep = kl >> 3, k8 = kl & 7;
            int tt = k8 & 3, hk = k8 >> 2;
            int dst = ((ntile * 2 + kstep) * 32 + (gc * 4 + tt)) * 2 + hk;
            Ws[bb][dst] = tf32cvt(W[(size_t)(kc * 16 + kl) * DD + n]);
        }
#pragma unroll
        for (int i = 0; i < 8; i++) {
            int idx = tid + 256 * i;
            int r  = idx >> 4;
            int kl = idx & 15;
            int row = rowBase + r;
            float xv = (row < NN) ? X[(size_t)row * DD + kc * 16 + kl] : 0.f;
            int tile = r >> 4, rr = r & 15;
            int gg = rr & 7, hr = rr >> 3;
            int kstep = kl >> 3, k8 = kl & 7;
            int tt = k8 & 3, hk = k8 >> 2;
            int dst = ((tile * 2 + kstep) * 32 + (gg * 4 + tt)) * 4 + (hr + 2 * hk);
            Xs[bb][dst] = tf32cvt(xv);
        }
    };

    stage(0, 0);
    __syncthreads();

    for (int kc = 0; kc < 8; kc++) {
        int bb = kc & 1;
        if (kc + 1 < 8) stage(kc + 1, bb ^ 1);
#pragma unroll
        for (int ks = 0; ks < 2; ks++) {
            uint2 bf[4];
#pragma unroll
            for (int j = 0; j < 4; j++)
                bf[j] = *(const uint2*)&Ws[bb][((wnT + j) * 2 + ks) * 64 + lane * 2];
#pragma unroll
            for (int i = 0; i < 4; i++) {
                uint4 av = *(const uint4*)&Xs[bb][((wmT + i) * 2 + ks) * 128 + lane * 4];
#pragma unroll
                for (int j = 0; j < 4; j++) {
                    asm volatile(
                        "mma.sync.aligned.m16n8k8.row.col.f32.tf32.tf32.f32 "
                        "{%0,%1,%2,%3}, {%4,%5,%6,%7}, {%8,%9}, {%0,%1,%2,%3};"
                        : "+f"(acc[i][j][0]), "+f"(acc[i][j][1]),
                          "+f"(acc[i][j][2]), "+f"(acc[i][j][3])
                        : "r"(av.x), "r"(av.y), "r"(av.z), "r"(av.w),
                          "r"(bf[j].x), "r"(bf[j].y));
                }
            }
        }
        __syncthreads();
    }

#pragma unroll
    for (int i = 0; i < 4; i++) {
        int rbase = rowBase + wm + i * 16 + g;
#pragma unroll
        for (int half = 0; half < 2; half++) {
            int r = rbase + half * 8;
            if (r < NN) {
                float2* p = (float2*)(g_h + (size_t)r * DD + wn);
#pragma unroll
                for (int j = 0; j < 4; j++)
                    p[j * 4 + t4] = make_float2(acc[i][j][half * 2],
                                                acc[i][j][half * 2 + 1]);
            }
        }
    }
}

// -- persistent gather + BN + final: 148 x 512 (proven geometry),
//    TWO nodes per warp with fused edge pipelines for 2x MLP. --
__global__ void __launch_bounds__(512, 1)
k_gatherF(const float* __restrict__ b,
          const float* __restrict__ gamma,
          const float* __restrict__ beta,
          const float* __restrict__ X,
          float* __restrict__ out) {
    __shared__ float s_sum[DD];
    __shared__ float s_sumsq[DD];
    __shared__ int s_last;
    int t = threadIdx.x;
    if (t < DD) { s_sum[t] = 0.f; s_sumsq[t] = 0.f; }
    __syncthreads();

    int lane = t & 31;
    int warp = t >> 5;                    // 0..15
    float4 bb = __ldg(&((const float4*)b)[lane]);

    // ---- phase 1: gather (2 nodes/warp) + per-block BN partials ----
    for (int tile = blockIdx.x; tile < GT32; tile += gridDim.x) {
        int n0 = tile * 32 + warp * 2;    // NN = 3125*32: always < NN
        int n1 = n0 + 1;
        float dv0 = g_dinv[n0], dv1 = g_dinv[n1];
        float4 h0 = __ldg(&((const float4*)(g_h + (size_t)n0 * DD))[lane]);
        float4 h1 = __ldg(&((const float4*)(g_h + (size_t)n1 * DD))[lane]);
        float q0 = dv0 * dv0, q1 = dv1 * dv1;
        float4 a0 = make_float4(h0.x * q0 + bb.x, h0.y * q0 + bb.y,
                                h0.z * q0 + bb.z, h0.w * q0 + bb.w);
        float4 a1 = make_float4(h1.x * q1 + bb.x, h1.y * q1 + bb.y,
                                h1.z * q1 + bb.z, h1.w * q1 + bb.w);
        int e0 = g_rowstart[n0], end0 = e0 + g_deg[n0];
        int e1 = g_rowstart[n1], end1 = e1 + g_deg[n1];
        // fused pipeline: 2 edges per node per iteration (~8 loads in flight)
        while (e0 + 1 < end0 && e1 + 1 < end1) {
            int2 ma = __ldg(&g_emeta[e0]), mc = __ldg(&g_emeta[e1]);
            int2 mb = __ldg(&g_emeta[e0 + 1]), md = __ldg(&g_emeta[e1 + 1]);
            float4 va = __ldg(&((const float4*)(g_h + (size_t)ma.x * DD))[lane]);
            float4 vc = __ldg(&((const float4*)(g_h + (size_t)mc.x * DD))[lane]);
            float4 vb = __ldg(&((const float4*)(g_h + (size_t)mb.x * DD))[lane]);
            float4 vd = __ldg(&((const float4*)(g_h + (size_t)md.x * DD))[lane]);
            float fa = __int_as_float(ma.y), fb = __int_as_float(mb.y);
            float fc = __int_as_float(mc.y), fd = __int_as_float(md.y);
            a0.x += va.x * fa + vb.x * fb; a0.y += va.y * fa + vb.y * fb;
            a0.z += va.z * fa + vb.z * fb; a0.w += va.w * fa + vb.w * fb;
            a1.x += vc.x * fc + vd.x * fd; a1.y += vc.y * fc + vd.y * fd;
            a1.z += vc.z * fc + vd.z * fd; a1.w += vc.w * fc + vd.w * fd;
            e0 += 2; e1 += 2;
        }
        for (; e0 < end0; e0++) {
            int2 m = __ldg(&g_emeta[e0]);
            float f = __int_as_float(m.y);
            float4 v = __ldg(&((const float4*)(g_h + (size_t)m.x * DD))[lane]);
            a0.x += v.x * f; a0.y += v.y * f; a0.z += v.z * f; a0.w += v.w * f;
        }
        for (; e1 < end1; e1++) {
            int2 m = __ldg(&g_emeta[e1]);
            float f = __int_as_float(m.y);
            float4 v = __ldg(&((const float4*)(g_h + (size_t)m.x * DD))[lane]);
            a1.x += v.x * f; a1.y += v.y * f; a1.z += v.z * f; a1.w += v.w * f;
        }
        ((float4*)(g_acc + (size_t)n0 * DD))[lane] = a0;
        ((float4*)(g_acc + (size_t)n1 * DD))[lane] = a1;
        int c = lane * 4;
        atomicAdd(&s_sum[c + 0], a0.x + a1.x);
        atomicAdd(&s_sum[c + 1], a0.y + a1.y);
        atomicAdd(&s_sum[c + 2], a0.z + a1.z);
        atomicAdd(&s_sum[c + 3], a0.w + a1.w);
        atomicAdd(&s_sumsq[c + 0], a0.x * a0.x + a1.x * a1.x);
        atomicAdd(&s_sumsq[c + 1], a0.y * a0.y + a1.y * a1.y);
        atomicAdd(&s_sumsq[c + 2], a0.z * a0.z + a1.z * a1.z);
        atomicAdd(&s_sumsq[c + 3], a0.w * a0.w + a1.w * a1.w);
    }
    __syncthreads();
    if (t < DD)            atomicAdd(&g_colsum[t], s_sum[t]);
    else if (t < 2 * DD)   atomicAdd(&g_colsumsq[t - DD], s_sumsq[t - DD]);

    // ---- grid-wide sync (148 blocks, 1 CTA/SM: proven) ----
    __threadfence();
    __syncthreads();
    if (t == 0) s_last = (atomicAdd(&g_ticket, 1) == (int)gridDim.x - 1);
    __syncthreads();
    if (s_last) {
        if (t < DD) {
            float mean = g_colsum[t] * (1.0f / (float)NN);
            float var  = g_colsumsq[t] * (1.0f / (float)NN) - mean * mean;
            float rstd = rsqrtf(var + 1e-5f);
            float sc   = rstd * gamma[t];
            g_scale[t] = sc;
            g_shift[t] = beta[t] - mean * sc;
        }
        __threadfence();
        __syncthreads();
        if (t == 0) atomicExch(&g_done, 1);
    }
    if (t == 0) { while (atomicAdd(&g_done, 0) == 0) { } }
    __syncthreads();

    // ---- phase 2: out = relu(acc*scale + shift) + x (2 nodes/warp) ----
    float4 sc = ((const float4*)g_scale)[lane];
    float4 sh = ((const float4*)g_shift)[lane];
    for (int tile = blockIdx.x; tile < GT32; tile += gridDim.x) {
        int n0 = tile * 32 + warp * 2;
#pragma unroll
        for (int k = 0; k < 2; k++) {
            size_t off = (size_t)(n0 + k) * DD;
            float4 a  = ((const float4*)(g_acc + off))[lane];
            float4 xv = __ldg(&((const float4*)(X + off))[lane]);
            float4 o;
            o.x = fmaxf(a.x * sc.x + sh.x, 0.f) + xv.x;
            o.y = fmaxf(a.y * sc.y + sh.y, 0.f) + xv.y;
            o.z = fmaxf(a.z * sc.z + sh.z, 0.f) + xv.z;
            o.w = fmaxf(a.w * sc.w + sh.w, 0.f) + xv.w;
            ((float4*)(out + off))[lane] = o;
        }
    }
}

// ---------------- launch ----------------
extern "C" void kernel_launch(void* const* d_in, const int* in_sizes, int n_in,
                              void* d_out, int out_size) {
    const float* x = nullptr; const void* ei = nullptr; const float* W = nullptr;
    const float* b = nullptr; const float* gamma = nullptr; const float* beta = nullptr;
    for (int i = 0; i < n_in; i++) {
        int sz = in_sizes[i];
        if (sz == NN * DD)      x  = (const float*)d_in[i];
        else if (sz == 2 * EE)  ei = d_in[i];
        else if (sz == DD * DD) W  = (const float*)d_in[i];
        else if (sz == DD) {
            if (!b) b = (const float*)d_in[i];
            else if (!gamma) gamma = (const float*)d_in[i];
            else beta = (const float*)d_in[i];
        }
    }
    float* out = (float*)d_out;

    static cudaStream_t s_side = nullptr;
    static cudaEvent_t ev_fork = nullptr, ev_join = nullptr;
    if (!s_side) {
        cudaStreamCreateWithFlags(&s_side, cudaStreamNonBlocking);
        cudaEventCreateWithFlags(&ev_fork, cudaEventDisableTiming);
        cudaEventCreateWithFlags(&ev_join, cudaEventDisableTiming);
    }

    // Fork: tensor-core GEMM overlaps the edge-prep chain.
    cudaEventRecord(ev_fork, 0);
    cudaStreamWaitEvent(s_side, ev_fork, 0);
    k_gemm<<<(NN + 127) / 128, 256, 0, s_side>>>(x, W);
    cudaEventRecord(ev_join, s_side);

    // Edge-prep chain.
    k_prep<<<(NN + 255) / 256, 256>>>(ei);
    k_degree<<<(EE + 255) / 256, 256>>>(ei);
    k_scanF<<<SCAN_BLOCKS, 1024>>>();
    k_fill<<<(EE + 255) / 256, 256>>>(ei);

    // Join, then persistent gather+BN+final (proven 148x512 geometry).
    cudaStreamWaitEvent(0, ev_join, 0);
    k_gatherF<<<148, 512>>>(b, gamma, beta, x, out);
}